// round 14
// baseline (speedup 1.0000x reference)
#include <cuda_runtime.h>
#include <cuda_bf16.h>

// CorrelationLayer: out[b,d,h,w] = (1/sqrt(C)) * sum_c x1[b,c,h,w] * x2pad[b,c,h+di,w+dj]
// 80 displacements. B=8, C=128, H=128, W=192, fp32.
// v12: R10 skeleton (6 px/thread, CHS=8, 2 buffers, persistent ticket) with
//      PACKED fma.rn.f32x2 compute: halves fma-pipe occupancy; acc = 27 u64.

#define CC   128
#define HH   128
#define WW   192
#define PW   96
#define PH   2
#define CHS  8
#define TX   16
#define NTHREADS 288
#define NSTAGES  16
#define HALO_H   10
#define HALO_W   104
#define S1_FLT   (CHS * PH * PW)          // 1536
#define S2_FLT   (CHS * HALO_H * HALO_W)  // 8320
#define S1_F4    (S1_FLT / 4)             // 384
#define S2_F4    (S2_FLT / 4)             // 2080
#define NTILES   (2 * 64 * 8)             // 1024
#define NBLK     296                      // 148 SMs * 2 blocks
#define GSTEP    ((unsigned)(CHS * HH * WW * 4))   // 786432 B
#define S1_BUFB  (S1_FLT * 4)             // 6144 B
#define S2_BUFB  (S2_FLT * 4)             // 33280 B
#define SLOT_B   (NTHREADS * 16)          // 4608 B

__device__ unsigned g_ticket;
__global__ void reset_ticket() { g_ticket = NBLK; }

__device__ __forceinline__ unsigned smem_u32(const void* p) {
    return (unsigned)__cvta_generic_to_shared(p);
}
__device__ __forceinline__ void cp16(unsigned dst, const char* base, unsigned off) {
    asm volatile("cp.async.cg.shared.global [%0], [%1], 16;\n"
                 :: "r"(dst), "l"(base + off));
}
__device__ __forceinline__ void sts_zero16(unsigned dst) {
    asm volatile("st.shared.v4.u32 [%0], {%1,%1,%1,%1};\n" :: "r"(dst), "r"(0u));
}
__device__ __forceinline__ void cp_commit() {
    asm volatile("cp.async.commit_group;\n" ::: "memory");
}
template <int N> __device__ __forceinline__ void cp_wait() {
    asm volatile("cp.async.wait_group %0;\n" :: "n"(N) : "memory");
}
__device__ __forceinline__ unsigned long long pk2(float lo, float hi) {
    unsigned long long r;
    asm("mov.b64 %0, {%1, %2};" : "=l"(r) : "f"(lo), "f"(hi));
    return r;
}
__device__ __forceinline__ void fma2(unsigned long long& d,
                                     unsigned long long a, unsigned long long b) {
    asm("fma.rn.f32x2 %0, %1, %2, %0;" : "+l"(d) : "l"(a), "l"(b));
}
__device__ __forceinline__ unsigned long long mul2(unsigned long long a,
                                                   unsigned long long b) {
    unsigned long long r;
    asm("mul.rn.f32x2 %0, %1, %2;" : "=l"(r) : "l"(a), "l"(b));
    return r;
}

__global__ __launch_bounds__(NTHREADS, 2)
void corr_kernel(const float* __restrict__ x1,
                 const float* __restrict__ x2,
                 float* __restrict__ out)
{
    __shared__ __align__(16) float s1[2][CHS][PH][PW];          // 12 KB
    __shared__ __align__(16) float s2[2][CHS][HALO_H][HALO_W];  // 65 KB
    __shared__ unsigned s_next;

    const int tid = threadIdx.x;
    const int tx  = tid & 15;
    const int hs  = (tid >> 4) & 1;
    const int w   = tid >> 5;
    const int pz  = hs;                       // diagonal pairing
    const int diI = hs ? (w + 8) % 9 : w;
    const int r2  = pz + diI;

    const char* base1 = (const char*)x1;
    const char* base2 = (const char*)x2;

    const unsigned s1base = smem_u32(&s1[0][0][0][0]) + 16u * tid;
    const unsigned s2base = smem_u32(&s2[0][0][0][0]) + 16u * tid;

    unsigned g1off[2];
    unsigned g2off[8];
    bool     pr[8];

    auto setup = [&](unsigned t) {
        int w0 = (int)(t & 1u) * PW;
        unsigned q = t >> 1;
        int h0 = (int)(q & 63u) * PH;
        int b  = (int)(q >> 6);
        #pragma unroll
        for (int sl = 0; sl < 2; sl++) {
            int i  = tid + NTHREADS * sl;
            int ii = (i < S1_F4) ? i : 0;
            int ch = ii / 48, rem = ii - ch * 48;
            int rr = rem / 24, c4 = rem - rr * 24;
            g1off[sl] = (unsigned)((((b * CC + ch) * HH + h0 + rr) * WW + w0 + 4 * c4) * 4);
        }
        #pragma unroll
        for (int sl = 0; sl < 8; sl++) {
            int i  = tid + NTHREADS * sl;
            int ii = (i < S2_F4) ? i : 0;
            int ch  = ii / 260, rem = ii - ch * 260;
            int rr  = rem / 26,  c4 = rem - rr * 26;
            int hr  = h0 - 4 + rr;
            int wc  = w0 - 4 + 4 * c4;
            pr[sl] = (i < S2_F4) && (hr >= 0) && (hr < HH) && (wc >= 0) && (wc < WW);
            int hrc = pr[sl] ? hr : 0;
            int wcc = pr[sl] ? wc : 0;
            g2off[sl] = (unsigned)((((b * CC + ch) * HH + hrc) * WW + wcc) * 4);
        }
    };

    auto issue = [&](int buf) {
        const unsigned b1 = buf ? (unsigned)S1_BUFB : 0u;
        const unsigned b2 = buf ? (unsigned)S2_BUFB : 0u;
        cp16(s1base + b1, base1, g1off[0]);
        if (tid < S1_F4 - NTHREADS)
            cp16(s1base + SLOT_B + b1, base1, g1off[1]);
        #pragma unroll
        for (int sl = 0; sl < 8; sl++) {
            const bool valid = (sl < 7) || (tid < S2_F4 - 7 * NTHREADS);
            if (valid) {
                unsigned dst = s2base + (unsigned)sl * SLOT_B + b2;
                if (pr[sl]) cp16(dst, base2, g2off[sl]);
                else        sts_zero16(dst);
            }
        }
        cp_commit();
    };

    unsigned long long acc[9][3];     // 9 dj x 3 pixel-pairs (6 px) packed f32x2
    #pragma unroll
    for (int j = 0; j < 9; j++)
        #pragma unroll
        for (int k = 0; k < 3; k++) acc[j][k] = 0ULL;

    unsigned t = blockIdx.x;
    setup(t);
    issue(0);
    unsigned gs = 0;

    const float scale = 0.08838834764831845f;   // 1/sqrt(128)
    const unsigned long long sc2 = pk2(scale, scale);

    for (;;) {
        unsigned q = t >> 1;
        unsigned obase = (((q >> 6) * 80u) * HH + ((q & 63u) * PH + pz)) * WW
                       + (t & 1u) * PW + 6 * tx;
        unsigned tnext = NTILES;

        #pragma unroll 1
        for (int st = 0; st < NSTAGES; st++, gs++) {
            const int bb = (int)(gs & 1u);
            cp_wait<0>();
            __syncthreads();

            if (st == 0) {
                if (tid == 0) s_next = atomicAdd(&g_ticket, 1u);
            }
            if (st < NSTAGES - 1) {
                g1off[0] += GSTEP; g1off[1] += GSTEP;
                #pragma unroll
                for (int sl = 0; sl < 8; sl++) g2off[sl] += GSTEP;
                issue(bb ^ 1);
            } else {
                tnext = s_next;
                if (tnext < NTILES) { setup(tnext); issue(bb ^ 1); }
            }

            const float* q1 = &s1[bb][0][pz][6 * tx];
            const float* q2 = &s2[bb][0][r2][6 * tx];
            #pragma unroll
            for (int ch = 0; ch < CHS; ch++) {
                const float* c1 = q1 + ch * (PH * PW);
                const float* c2 = q2 + ch * (HALO_H * HALO_W);
                float2 a01 = *(const float2*)(c1);
                float2 a23 = *(const float2*)(c1 + 2);
                float2 a45 = *(const float2*)(c1 + 4);
                float2 w0_ = *(const float2*)(c2);
                float2 w1_ = *(const float2*)(c2 + 2);
                float2 w2_ = *(const float2*)(c2 + 4);
                float2 w3_ = *(const float2*)(c2 + 6);
                float2 w4_ = *(const float2*)(c2 + 8);
                float2 w5_ = *(const float2*)(c2 + 10);
                float2 w6_ = *(const float2*)(c2 + 12);
                float v[14] = {w0_.x, w0_.y, w1_.x, w1_.y, w2_.x, w2_.y,
                               w3_.x, w3_.y, w4_.x, w4_.y, w5_.x, w5_.y,
                               w6_.x, w6_.y};

                unsigned long long A0 = pk2(a01.x, a01.y);
                unsigned long long A1 = pk2(a23.x, a23.y);
                unsigned long long A2 = pk2(a45.x, a45.y);

                unsigned long long P[13];
                #pragma unroll
                for (int i = 0; i < 13; i++) P[i] = pk2(v[i], v[i + 1]);

                #pragma unroll
                for (int j = 0; j < 9; j++) {
                    fma2(acc[j][0], A0, P[j]);
                    fma2(acc[j][1], A1, P[j + 2]);
                    fma2(acc[j][2], A2, P[j + 4]);
                }
            }
        }

        // ---- epilogue (overlaps the already-issued next-tile loads) ----
        #pragma unroll
        for (int j = 0; j < 9; j++) {
            int lin = diI * 9 + j;
            if (lin == 40) continue;               // (0,0) displacement
            int d = lin - (lin > 40 ? 1 : 0);
            float* dst = &out[obase + (unsigned)d * (HH * WW)];
            *(unsigned long long*)(dst)     = mul2(acc[j][0], sc2);
            *(unsigned long long*)(dst + 2) = mul2(acc[j][1], sc2);
            *(unsigned long long*)(dst + 4) = mul2(acc[j][2], sc2);
        }

        if (tnext >= NTILES) break;
        #pragma unroll
        for (int j = 0; j < 9; j++)
            #pragma unroll
            for (int k = 0; k < 3; k++) acc[j][k] = 0ULL;
        t = tnext;
    }
}

extern "C" void kernel_launch(void* const* d_in, const int* in_sizes, int n_in,
                              void* d_out, int out_size)
{
    const float* x1 = (const float*)d_in[0];
    const float* x2 = (const float*)d_in[1];
    float* out = (float*)d_out;

    reset_ticket<<<1, 1>>>();
    corr_kernel<<<NBLK, NTHREADS>>>(x1, x2, out);
}